// round 2
// baseline (speedup 1.0000x reference)
#include <cuda_runtime.h>
#include <math.h>
#include <stdint.h>

#define BB   64
#define LL   1024
#define EE   80
#define HH   512
#define DEE  512
#define VV   500
#define KXX  (EE + HH)     // 592
#define FH   (4 * HH)      // 2048

// ---------------- scratch (no allocations allowed) ----------------
__device__ float g_h[BB * HH];
__device__ float g_u[BB * HH];
__device__ float g_alpha[BB * LL];      // scores, then softmax'd in place
__device__ float g_ctx[BB * DEE];
__device__ float g_newo[BB * 512];

// Fast tanh: 2 MUFU ops, abs err ~1e-6. Saturates correctly at +/-inf.
__device__ __forceinline__ float fast_tanh(float x) {
    return 1.0f - __fdividef(2.0f, __expf(2.0f * x) + 1.0f);
}
__device__ __forceinline__ float sigm(float x) {
    return 1.0f / (1.0f + expf(-x));
}

// =====================================================================
// Kernel 1: LSTM cell.  z = [inputs,o_prev]@Wk + h_prev@Uk + b ; gates.
// grid (4 j-tiles, 16 b-tiles), block 128.  BT=4 batches per block.
// =====================================================================
__global__ void lstm_kernel(const float* __restrict__ inputs,
                            const float* __restrict__ o_prev,
                            const float* __restrict__ h_prev,
                            const float* __restrict__ c_prev,
                            const float* __restrict__ Wk,
                            const float* __restrict__ Uk,
                            const float* __restrict__ bias,
                            float* __restrict__ out_h,
                            float* __restrict__ out_c)
{
    const int BT = 4;
    __shared__ float xs[BT][KXX];
    __shared__ float hs[BT][HH];
    const int tid = threadIdx.x;
    const int jg  = blockIdx.x * 128 + tid;    // gate column 0..511
    const int b0  = blockIdx.y * BT;

    for (int idx = tid; idx < BT * KXX; idx += 128) {
        int bb = idx / KXX, k = idx % KXX;
        xs[bb][k] = (k < EE) ? inputs[(b0 + bb) * EE + k]
                             : o_prev[(b0 + bb) * HH + (k - EE)];
    }
    for (int idx = tid; idx < BT * HH; idx += 128)
        hs[idx / HH][idx % HH] = h_prev[b0 * HH + idx];
    __syncthreads();

    float a0[BT] = {0.f, 0.f, 0.f, 0.f};
    float a1[BT] = {0.f, 0.f, 0.f, 0.f};
    float a2[BT] = {0.f, 0.f, 0.f, 0.f};
    float a3[BT] = {0.f, 0.f, 0.f, 0.f};

    for (int k = 0; k < KXX; k++) {
        const float* wr = Wk + (size_t)k * FH;
        float w0 = wr[jg], w1 = wr[jg + HH], w2 = wr[jg + 2 * HH], w3 = wr[jg + 3 * HH];
        #pragma unroll
        for (int bb = 0; bb < BT; bb++) {
            float xv = xs[bb][k];
            a0[bb] += w0 * xv; a1[bb] += w1 * xv;
            a2[bb] += w2 * xv; a3[bb] += w3 * xv;
        }
    }
    for (int k = 0; k < HH; k++) {
        const float* wr = Uk + (size_t)k * FH;
        float w0 = wr[jg], w1 = wr[jg + HH], w2 = wr[jg + 2 * HH], w3 = wr[jg + 3 * HH];
        #pragma unroll
        for (int bb = 0; bb < BT; bb++) {
            float hv = hs[bb][k];
            a0[bb] += w0 * hv; a1[bb] += w1 * hv;
            a2[bb] += w2 * hv; a3[bb] += w3 * hv;
        }
    }

    const float bi = bias[jg], bf = bias[jg + HH],
                bg = bias[jg + 2 * HH], bo = bias[jg + 3 * HH];
    #pragma unroll
    for (int bb = 0; bb < BT; bb++) {
        int b = b0 + bb;
        float ig = sigm(a0[bb] + bi);
        float fg = sigm(a1[bb] + bf);
        float gg = tanhf(a2[bb] + bg);
        float og = sigm(a3[bb] + bo);
        float c  = fg * c_prev[b * HH + jg] + ig * gg;
        float h  = og * tanhf(c);
        out_c[b * HH + jg] = c;
        out_h[b * HH + jg] = h;
        g_h[b * HH + jg]   = h;
    }
}

// =====================================================================
// Kernel 2: u = h @ W2h   (64x512, K=512).  grid 64 (one b), block 512.
// =====================================================================
__global__ void u_kernel(const float* __restrict__ W2h)
{
    __shared__ float hsh[HH];
    const int b = blockIdx.x, j = threadIdx.x;
    hsh[j] = g_h[b * HH + j];
    __syncthreads();
    float acc = 0.f;
    #pragma unroll 8
    for (int k = 0; k < HH; k++)
        acc += hsh[k] * W2h[(size_t)k * HH + j];
    g_u[b * HH + j] = acc;
}

// =====================================================================
// Kernel 3 (dominant): fused  scores[b,l] = sum_d tanh((seq@W1e)[b,l,d]
//                                              + u[b,d]) * beta[d]
// 128-row x 64-col register-tiled fp32 GEMM, K=512, 8 n-chunks per block.
// grid (L/128 = 8, B = 64) = 512 blocks, block 256 threads.
// Thread tile: 8(m) x 4(n).  tx = tid&15 (n), ty = tid>>4 (m-group).
// =====================================================================
__global__ void __launch_bounds__(256, 2)
scores_kernel(const float* __restrict__ seq,
              const float* __restrict__ W1e,
              const float* __restrict__ beta)
{
    __shared__ __align__(16) float As[32][132];   // [k][m], padded
    __shared__ __align__(16) float Bs[32][64];    // [k][n]
    __shared__ float ush[512];
    __shared__ float bsh[512];

    const int b   = blockIdx.y;
    const int l0  = blockIdx.x * 128;
    const int tid = threadIdx.x;
    const int tx  = tid & 15;
    const int ty  = tid >> 4;

    for (int i = tid; i < 512; i += 256) {
        ush[i] = g_u[b * 512 + i];
        bsh[i] = beta[i];
    }

    const float* seqb = seq + ((size_t)b * LL + l0) * 512;

    float sacc[8];
    #pragma unroll
    for (int mi = 0; mi < 8; mi++) sacc[mi] = 0.f;

    // loader mappings (constant across tiles)
    const int ldA_r  = tid >> 1;
    const int ldA_kb = (tid & 1) * 16;
    const int ldB_k  = tid >> 3;
    const int ldB_c  = (tid & 7) * 8;

    for (int nc = 0; nc < 8; nc++) {
        const int n0 = nc * 64;
        float acc[8][4];
        #pragma unroll
        for (int mi = 0; mi < 8; mi++)
            #pragma unroll
            for (int ni = 0; ni < 4; ni++) acc[mi][ni] = 0.f;

        for (int kt = 0; kt < 16; kt++) {
            const int k0 = kt * 32;
            __syncthreads();   // previous-tile consumers done before overwrite
            {
                const float* src = seqb + (size_t)ldA_r * 512 + k0 + ldA_kb;
                #pragma unroll
                for (int i = 0; i < 16; i++) As[ldA_kb + i][ldA_r] = src[i];
            }
            {
                const float* src = W1e + (size_t)(k0 + ldB_k) * 512 + n0 + ldB_c;
                #pragma unroll
                for (int i = 0; i < 8; i++) Bs[ldB_k][ldB_c + i] = src[i];
            }
            __syncthreads();

            #pragma unroll
            for (int k = 0; k < 32; k++) {
                float4 av0 = *(const float4*)&As[k][ty * 8];
                float4 av1 = *(const float4*)&As[k][ty * 8 + 4];
                float4 bv  = *(const float4*)&Bs[k][tx * 4];
                float am[8] = {av0.x, av0.y, av0.z, av0.w,
                               av1.x, av1.y, av1.z, av1.w};
                float bn[4] = {bv.x, bv.y, bv.z, bv.w};
                #pragma unroll
                for (int mi = 0; mi < 8; mi++)
                    #pragma unroll
                    for (int ni = 0; ni < 4; ni++)
                        acc[mi][ni] += am[mi] * bn[ni];
            }
        }

        // epilogue: tanh(A + u) * beta, reduce over this n-chunk
        #pragma unroll
        for (int mi = 0; mi < 8; mi++) {
            float s = 0.f;
            #pragma unroll
            for (int ni = 0; ni < 4; ni++) {
                int n = n0 + tx * 4 + ni;
                s += fast_tanh(acc[mi][ni] + ush[n]) * bsh[n];
            }
            sacc[mi] += s;
        }
    }

    // reduce across the 16 tx lanes sharing each m-row
    #pragma unroll
    for (int mi = 0; mi < 8; mi++) {
        float s = sacc[mi];
        #pragma unroll
        for (int off = 8; off > 0; off >>= 1)
            s += __shfl_xor_sync(0xFFFFFFFF, s, off);
        if (tx == 0)
            g_alpha[b * LL + l0 + ty * 8 + mi] = s;
    }
}

// =====================================================================
// Kernel 4: softmax over L per batch (in place in g_alpha).
// =====================================================================
__global__ void softmax_kernel()
{
    __shared__ float red[256];
    const int b = blockIdx.x, tid = threadIdx.x;
    float v[4];
    float mx = -1e30f;
    #pragma unroll
    for (int i = 0; i < 4; i++) {
        v[i] = g_alpha[b * LL + i * 256 + tid];
        mx = fmaxf(mx, v[i]);
    }
    red[tid] = mx; __syncthreads();
    for (int s = 128; s > 0; s >>= 1) {
        if (tid < s) red[tid] = fmaxf(red[tid], red[tid + s]);
        __syncthreads();
    }
    mx = red[0]; __syncthreads();

    float sum = 0.f;
    #pragma unroll
    for (int i = 0; i < 4; i++) {
        v[i] = __expf(v[i] - mx);
        sum += v[i];
    }
    red[tid] = sum; __syncthreads();
    for (int s = 128; s > 0; s >>= 1) {
        if (tid < s) red[tid] += red[tid + s];
        __syncthreads();
    }
    float inv = __fdividef(1.0f, red[0]);
    #pragma unroll
    for (int i = 0; i < 4; i++)
        g_alpha[b * LL + i * 256 + tid] = v[i] * inv;
}

// =====================================================================
// Kernel 5: ctx[b,d] = sum_l alpha[b,l] * seq[b,l,d].  grid (64,2) x 256.
// =====================================================================
__global__ void ctx_kernel(const float* __restrict__ seq)
{
    __shared__ float al[LL];
    const int b = blockIdx.x;
    const int d = blockIdx.y * 256 + threadIdx.x;
    for (int i = threadIdx.x; i < LL; i += 256)
        al[i] = g_alpha[b * LL + i];
    __syncthreads();

    const float* sp = seq + (size_t)b * LL * 512 + d;
    float acc0 = 0.f, acc1 = 0.f;
    #pragma unroll 8
    for (int l = 0; l < LL; l += 2) {
        acc0 += al[l]     * sp[(size_t)l * 512];
        acc1 += al[l + 1] * sp[(size_t)(l + 1) * 512];
    }
    g_ctx[b * DEE + d] = acc0 + acc1;
}

// =====================================================================
// Kernel 6: new_o = tanh([h, ctx] @ W3o).  grid 32, block 512, BT=2.
// =====================================================================
__global__ void newo_kernel(const float* __restrict__ W3o,
                            float* __restrict__ out_newo)
{
    const int BT = 2;
    __shared__ float hc[BT][1024];
    const int b0 = blockIdx.x * BT;
    const int j  = threadIdx.x;
    for (int idx = j; idx < BT * 1024; idx += 512) {
        int bb = idx / 1024, k = idx % 1024;
        hc[bb][k] = (k < 512) ? g_h[(b0 + bb) * 512 + k]
                              : g_ctx[(b0 + bb) * 512 + (k - 512)];
    }
    __syncthreads();
    float a[BT] = {0.f, 0.f};
    #pragma unroll 4
    for (int k = 0; k < 1024; k++) {
        float w = W3o[(size_t)k * 512 + j];
        #pragma unroll
        for (int bb = 0; bb < BT; bb++) a[bb] += hc[bb][k] * w;
    }
    #pragma unroll
    for (int bb = 0; bb < BT; bb++) {
        float t = tanhf(a[bb]);
        g_newo[(b0 + bb) * 512 + j]    = t;
        out_newo[(b0 + bb) * 512 + j]  = t;
    }
}

// =====================================================================
// Kernel 7: logits = new_o @ W4.  grid 32, block 512 (500 active), BT=2.
// =====================================================================
__global__ void logits_kernel(const float* __restrict__ W4,
                              float* __restrict__ out_logits)
{
    const int BT = 2;
    __shared__ float no[BT][512];
    const int b0 = blockIdx.x * BT;
    const int j  = threadIdx.x;
    for (int idx = j; idx < BT * 512; idx += 512)
        no[idx / 512][idx % 512] = g_newo[b0 * 512 + idx];
    __syncthreads();
    if (j < VV) {
        float a[BT] = {0.f, 0.f};
        #pragma unroll 4
        for (int k = 0; k < 512; k++) {
            float w = W4[(size_t)k * VV + j];
            #pragma unroll
            for (int bb = 0; bb < BT; bb++) a[bb] += no[bb][k] * w;
        }
        #pragma unroll
        for (int bb = 0; bb < BT; bb++)
            out_logits[(b0 + bb) * VV + j] = a[bb];
    }
}

// =====================================================================
extern "C" void kernel_launch(void* const* d_in, const int* in_sizes, int n_in,
                              void* d_out, int out_size)
{
    (void)in_sizes; (void)n_in; (void)out_size;
    const float* inputs = (const float*)d_in[0];
    const float* seq    = (const float*)d_in[1];
    const float* h_prev = (const float*)d_in[2];
    const float* c_prev = (const float*)d_in[3];
    const float* o_prev = (const float*)d_in[4];
    const float* Wk     = (const float*)d_in[5];
    const float* Uk     = (const float*)d_in[6];
    const float* bias   = (const float*)d_in[7];
    const float* W1e    = (const float*)d_in[8];
    const float* W2h    = (const float*)d_in[9];
    const float* beta   = (const float*)d_in[10];
    const float* W3o    = (const float*)d_in[11];
    const float* W4     = (const float*)d_in[12];

    float* out        = (float*)d_out;
    float* out_logits = out;                         // 64*500
    float* out_h      = out + BB * VV;               // 64*512
    float* out_c      = out_h + BB * HH;             // 64*512
    float* out_newo   = out_c + BB * HH;             // 64*512

    lstm_kernel  <<<dim3(4, 16), 128>>>(inputs, o_prev, h_prev, c_prev,
                                        Wk, Uk, bias, out_h, out_c);
    u_kernel     <<<64, 512>>>(W2h);
    scores_kernel<<<dim3(8, 64), 256>>>(seq, W1e, beta);
    softmax_kernel<<<64, 256>>>();
    ctx_kernel   <<<dim3(64, 2), 256>>>(seq);
    newo_kernel  <<<32, 512>>>(W3o, out_newo);
    logits_kernel<<<32, 512>>>(W4, out_logits);
}